// round 3
// baseline (speedup 1.0000x reference)
#include <cuda_runtime.h>
#include <math.h>

// Problem constants
#define Bb 2
#define Ss 2048
#define Dd 1024
#define Hh 16
#define HDc 64
static __device__ __constant__ const float kEPS = 1e-8f;
#define SCALE 0.125f  /* 1/sqrt(64) */

// Scratch (no allocations allowed -> device globals)
__device__ float g_Q[Bb * Hh * Ss * HDc];     // [B,H,S,HD]
__device__ float g_K[Bb * Hh * Ss * HDc];     // [B,H,S,HD]
__device__ float g_attn[Bb * Ss * Dd];        // [B,S,D]

// ---------------------------------------------------------------------------
// SGEMM: C[r][c] = sum_k A[r][k] * W[c][k] + bias[c]
// BM=BN=128, BK=16, 256 threads, 8x8 per-thread microkernel.
// mode 0: scatter into g_Q / g_K (QK projection, N=2048)
// mode 1: A is g_attn (device global), write plain to Cout (out proj, N=1024)
// ---------------------------------------------------------------------------
__global__ void __launch_bounds__(256)
sgemm_k(const float* __restrict__ A, const float* __restrict__ Wt,
        const float* __restrict__ bias, float* __restrict__ Cout, int mode)
{
    __shared__ float As[16][132];   // [k][r], padded
    __shared__ float Bs[16][132];   // [k][c], padded

    const float* __restrict__ Ain = (mode == 1) ? g_attn : A;

    const int tid = threadIdx.x;
    const int tx = tid & 15, ty = tid >> 4;
    const int rowBase = blockIdx.y * 128;
    const int colBase = blockIdx.x * 128;

    float acc[8][8];
#pragma unroll
    for (int i = 0; i < 8; i++)
#pragma unroll
        for (int j = 0; j < 8; j++) acc[i][j] = 0.f;

    for (int kt = 0; kt < Dd; kt += 16) {
#pragma unroll
        for (int t = 0; t < 2; t++) {
            int lin = tid + t * 256;          // 0..511
            int r   = lin >> 2;               // 0..127
            int kk  = (lin & 3) << 2;         // 0,4,8,12
            float4 v = *(const float4*)(Ain + (size_t)(rowBase + r) * Dd + kt + kk);
            As[kk + 0][r] = v.x; As[kk + 1][r] = v.y;
            As[kk + 2][r] = v.z; As[kk + 3][r] = v.w;
            float4 w = *(const float4*)(Wt + (size_t)(colBase + r) * Dd + kt + kk);
            Bs[kk + 0][r] = w.x; Bs[kk + 1][r] = w.y;
            Bs[kk + 2][r] = w.z; Bs[kk + 3][r] = w.w;
        }
        __syncthreads();
#pragma unroll
        for (int k = 0; k < 16; k++) {
            float a[8], b[8];
            *(float4*)(a + 0) = *(const float4*)&As[k][ty * 8];
            *(float4*)(a + 4) = *(const float4*)&As[k][ty * 8 + 4];
            *(float4*)(b + 0) = *(const float4*)&Bs[k][tx * 8];
            *(float4*)(b + 4) = *(const float4*)&Bs[k][tx * 8 + 4];
#pragma unroll
            for (int i = 0; i < 8; i++)
#pragma unroll
                for (int j = 0; j < 8; j++)
                    acc[i][j] += a[i] * b[j];
        }
        __syncthreads();
    }

    // Epilogue
#pragma unroll
    for (int i = 0; i < 8; i++) {
        int r  = rowBase + ty * 8 + i;
        int bb = r >> 11;                 // r / S
        int s  = r & 2047;                // r % S
#pragma unroll
        for (int jj = 0; jj < 8; jj += 4) {
            int c = colBase + tx * 8 + jj;
            float4 bv = *(const float4*)(bias + c);
            float4 v = make_float4(acc[i][jj + 0] + bv.x, acc[i][jj + 1] + bv.y,
                                   acc[i][jj + 2] + bv.z, acc[i][jj + 3] + bv.w);
            if (mode == 0) {
                float* dst;
                if (c < Dd) {
                    int h = c >> 6, d0 = c & 63;
                    dst = &g_Q[((size_t)(bb * Hh + h) * Ss + s) * HDc + d0];
                } else {
                    int c2 = c - Dd;
                    int h = c2 >> 6, d0 = c2 & 63;
                    dst = &g_K[((size_t)(bb * Hh + h) * Ss + s) * HDc + d0];
                }
                *(float4*)dst = v;
            } else {
                *(float4*)(Cout + (size_t)r * Dd + c) = v;
            }
        }
    }
}

// ---------------------------------------------------------------------------
// Flash-style attention with multiplicative mask and L1 renorm.
// out[r] = sum_t exp(s-m)*M*V / (sum_t exp(s-m)*M + EPS * sum_t exp(s-m))
// (invariant to the running max m, so EPS handled exactly.)
// One CTA per (b,h, 64-query tile). 256 threads, 4x4 microkernel over 64x64.
// ---------------------------------------------------------------------------
__device__ __forceinline__ float red16max(float v) {
#pragma unroll
    for (int o = 8; o; o >>= 1) v = fmaxf(v, __shfl_xor_sync(0xffffffffu, v, o));
    return v;
}
__device__ __forceinline__ float red16sum(float v) {
#pragma unroll
    for (int o = 8; o; o >>= 1) v += __shfl_xor_sync(0xffffffffu, v, o);
    return v;
}

__global__ void __launch_bounds__(256)
attn_k(const float* __restrict__ Vg, const float* __restrict__ Mg)
{
    // 3 x 16KB = 48KB static smem (exactly at the limit)
    __shared__ float Qs[64 * 64];    // transposed [d][r], xor-swizzled
    __shared__ float KVs[64 * 64];   // K: transposed [d][c] swizzled; V: natural [c][dd]
    __shared__ float Ps[64 * 64];    // transposed [c][r], xor-swizzled

    const int tid = threadIdx.x;
    const int tx = tid & 15, ty = tid >> 4;
    const int bh = blockIdx.y;            // b*16 + h
    const int bb = bh >> 4, h = bh & 15;
    const int q0 = blockIdx.x * 64;

    const float* __restrict__ gQ = g_Q + ((size_t)bh * Ss + q0) * HDc;
    const float* __restrict__ gK = g_K + (size_t)bh * Ss * HDc;

    // Load Q tile (once): transposed + swizzled
#pragma unroll
    for (int t = 0; t < 4; t++) {
        int lin = tid + t * 256;
        int col = lin & 63;               // dim
        int r4  = (lin >> 6) << 2;        // row group
        int sw  = (col & 15) << 2;
#pragma unroll
        for (int i = 0; i < 4; i++)
            Qs[col * 64 + ((r4 + i) ^ sw)] = gQ[(r4 + i) * HDc + col];
    }

    float m_cur[4], Zs[4], Ws[4], oacc[4][4];
#pragma unroll
    for (int i = 0; i < 4; i++) {
        m_cur[i] = -1e30f; Zs[i] = 0.f; Ws[i] = 0.f;
#pragma unroll
        for (int j = 0; j < 4; j++) oacc[i][j] = 0.f;
    }

    for (int kt = 0; kt < Ss; kt += 64) {
        __syncthreads();   // prev GEMM2 done with KVs/Ps; Q store visible (first iter)

        // Load K tile: transposed + swizzled into KVs
        const float* __restrict__ gKt = gK + (size_t)kt * HDc;
#pragma unroll
        for (int t = 0; t < 4; t++) {
            int lin = tid + t * 256;
            int col = lin & 63;
            int r4  = (lin >> 6) << 2;
            int sw  = (col & 15) << 2;
#pragma unroll
            for (int i = 0; i < 4; i++)
                KVs[col * 64 + ((r4 + i) ^ sw)] = gKt[(r4 + i) * HDc + col];
        }
        __syncthreads();

        // GEMM1: S = Q K^T
        float sacc[4][4];
#pragma unroll
        for (int i = 0; i < 4; i++)
#pragma unroll
            for (int j = 0; j < 4; j++) sacc[i][j] = 0.f;
#pragma unroll 8
        for (int d = 0; d < 64; d++) {
            const int sw = (d & 15) << 2;
            float qa[4], kb[4];
            *(float4*)qa = *(const float4*)&Qs[d * 64 + ((ty << 2) ^ sw)];
            *(float4*)kb = *(const float4*)&KVs[d * 64 + ((tx << 2) ^ sw)];
#pragma unroll
            for (int i = 0; i < 4; i++)
#pragma unroll
                for (int j = 0; j < 4; j++)
                    sacc[i][j] += qa[i] * kb[j];
        }

        // Row stats + masked exp + P store
        float mnew[4], alpha[4], zp[4], wp[4];
#pragma unroll
        for (int i = 0; i < 4; i++) {
            float rmax = -1e30f;
#pragma unroll
            for (int j = 0; j < 4; j++) {
                sacc[i][j] *= SCALE;
                rmax = fmaxf(rmax, sacc[i][j]);
            }
            rmax = red16max(rmax);
            mnew[i]  = fmaxf(m_cur[i], rmax);
            alpha[i] = __expf(m_cur[i] - mnew[i]);

            const float* mrow = Mg + ((size_t)(bb * Ss + q0 + (ty << 2) + i)) * Ss
                                   + kt + (tx << 2);
            float4 mv = *(const float4*)mrow;
            float p0 = __expf(sacc[i][0] - mnew[i]);
            float p1 = __expf(sacc[i][1] - mnew[i]);
            float p2 = __expf(sacc[i][2] - mnew[i]);
            float p3 = __expf(sacc[i][3] - mnew[i]);
            zp[i] = (p0 + p1) + (p2 + p3);
            float w0 = p0 * mv.x, w1 = p1 * mv.y, w2 = p2 * mv.z, w3 = p3 * mv.w;
            wp[i] = (w0 + w1) + (w2 + w3);

            int r = (ty << 2) + i;
            int c0 = (tx << 2);
            Ps[(c0 + 0) * 64 + (r ^ (((c0 + 0) & 15) << 2))] = w0;
            Ps[(c0 + 1) * 64 + (r ^ (((c0 + 1) & 15) << 2))] = w1;
            Ps[(c0 + 2) * 64 + (r ^ (((c0 + 2) & 15) << 2))] = w2;
            Ps[(c0 + 3) * 64 + (r ^ (((c0 + 3) & 15) << 2))] = w3;
        }
#pragma unroll
        for (int i = 0; i < 4; i++) {
            zp[i] = red16sum(zp[i]);
            wp[i] = red16sum(wp[i]);
            Zs[i] = Zs[i] * alpha[i] + zp[i];
            Ws[i] = Ws[i] * alpha[i] + wp[i];
            m_cur[i] = mnew[i];
        }
        __syncthreads();   // Ps visible; GEMM1 K-reads complete

        // Load V tile (natural [c][dd]) into KVs
        const float* __restrict__ gV = Vg + ((size_t)(bb * Ss + kt) * Hh + h) * HDc;
#pragma unroll
        for (int t = 0; t < 4; t++) {
            int lin4 = tid + t * 256;         // 0..1023
            int c    = lin4 >> 4;             // 0..63
            int dd4  = (lin4 & 15) << 2;
            *(float4*)&KVs[c * 64 + dd4] =
                *(const float4*)(gV + (size_t)c * (Hh * HDc) + dd4);
        }
        __syncthreads();

        // GEMM2: O += P V (with per-row rescale)
#pragma unroll
        for (int i = 0; i < 4; i++)
#pragma unroll
            for (int j = 0; j < 4; j++) oacc[i][j] *= alpha[i];
#pragma unroll 8
        for (int c = 0; c < 64; c++) {
            const int sw = (c & 15) << 2;
            float pa[4], vb[4];
            *(float4*)pa = *(const float4*)&Ps[c * 64 + ((ty << 2) ^ sw)];
            *(float4*)vb = *(const float4*)&KVs[c * 64 + (tx << 2)];
#pragma unroll
            for (int i = 0; i < 4; i++)
#pragma unroll
                for (int j = 0; j < 4; j++)
                    oacc[i][j] += pa[i] * vb[j];
        }
    }

    // Epilogue: divide and write [B,S,D] layout
#pragma unroll
    for (int i = 0; i < 4; i++) {
        float inv = 1.f / (Ws[i] + 1e-8f * Zs[i]);
        int s = q0 + (ty << 2) + i;
        float4 v = make_float4(oacc[i][0] * inv, oacc[i][1] * inv,
                               oacc[i][2] * inv, oacc[i][3] * inv);
        *(float4*)&g_attn[((size_t)(bb * Ss + s)) * Dd + h * HDc + (tx << 2)] = v;
    }
}

// ---------------------------------------------------------------------------
extern "C" void kernel_launch(void* const* d_in, const int* in_sizes, int n_in,
                              void* d_out, int out_size)
{
    const float* x     = (const float*)d_in[0];
    const float* V     = (const float*)d_in[1];
    const float* M     = (const float*)d_in[2];
    const float* in_w  = (const float*)d_in[3];
    const float* in_b  = (const float*)d_in[4];
    const float* out_w = (const float*)d_in[5];
    const float* out_b = (const float*)d_in[6];
    float* out = (float*)d_out;

    // 1) QK projection: [4096,1024] x [2048,1024]^T -> scatter to g_Q/g_K
    sgemm_k<<<dim3(16, 32), 256>>>(x, in_w, in_b, nullptr, 0);
    // 2) masked-renorm flash attention -> g_attn [B,S,D]
    attn_k<<<dim3(32, 32), 256>>>(V, M);
    // 3) out projection: g_attn x out_w^T + out_b -> d_out
    sgemm_k<<<dim3(8, 32), 256>>>(nullptr, out_w, out_b, out, 1);
}

// round 6
// speedup vs baseline: 1.3439x; 1.3439x over previous
#include <cuda_runtime.h>
#include <math.h>

// Problem constants
#define Bb 2
#define Ss 2048
#define Dd 1024
#define Hh 16
#define HDc 64
#define SCALE 0.125f  /* 1/sqrt(64) */

// Scratch (no allocations allowed -> device globals)
__device__ float g_Q[Bb * Hh * Ss * HDc];     // [B,H,S,HD]
__device__ float g_K[Bb * Hh * Ss * HDc];     // [B,H,S,HD]
__device__ float g_attn[Bb * Ss * Dd];        // [B,S,D]

// ---------------------------------------------------------------------------
// tf32 helpers: mma.m16n8k8 + 3xTF32 split for ~fp32 accuracy
// Fragment layouts (PTX ISA, m16n8k8 tf32, row.col):
//   g = lane>>2, tg = lane&3
//   A(16x8):  a0=(g,tg) a1=(g+8,tg) a2=(g,tg+4) a3=(g+8,tg+4)
//   B(8x8):   b0=(tg,g) b1=(tg+4,g)
//   C(16x8):  c0=(g,2tg) c1=(g,2tg+1) c2=(g+8,2tg) c3=(g+8,2tg+1)
// ---------------------------------------------------------------------------
__device__ __forceinline__ unsigned f2tf(float f) {
    unsigned u; asm("cvt.rna.tf32.f32 %0, %1;" : "=r"(u) : "f"(f)); return u;
}
struct HL { unsigned h, l; };
__device__ __forceinline__ HL splitf(float a) {
    HL r; r.h = f2tf(a);
    r.l = f2tf(a - __uint_as_float(r.h));
    return r;
}
__device__ __forceinline__ void mma8(float* c, unsigned a0, unsigned a1, unsigned a2,
                                     unsigned a3, unsigned b0, unsigned b1) {
    asm volatile("mma.sync.aligned.m16n8k8.row.col.f32.tf32.tf32.f32 "
                 "{%0,%1,%2,%3}, {%4,%5,%6,%7}, {%8,%9}, {%0,%1,%2,%3};"
                 : "+f"(c[0]), "+f"(c[1]), "+f"(c[2]), "+f"(c[3])
                 : "r"(a0), "r"(a1), "r"(a2), "r"(a3), "r"(b0), "r"(b1));
}
__device__ __forceinline__ void mma_x3(float* c, const HL a[4], HL b0, HL b1) {
    mma8(c, a[0].h, a[1].h, a[2].h, a[3].h, b0.h, b1.h);
    mma8(c, a[0].h, a[1].h, a[2].h, a[3].h, b0.l, b1.l);
    mma8(c, a[0].l, a[1].l, a[2].l, a[3].l, b0.h, b1.h);
}

// ---------------------------------------------------------------------------
// Projection GEMM (3xTF32): C[r][c] = sum_k A[r][k] * W[c][k] + bias[c]
// BM=128, BN=64, BK=32, 256 threads = 8 warps (4m x 2n), warp tile 32x32.
// mode 0: scatter into g_Q / g_K (QK projection, N=2048)
// mode 1: A is g_attn, write plain to Cout (out projection, N=1024)
// ---------------------------------------------------------------------------
__global__ void __launch_bounds__(256)
proj_k(const float* __restrict__ A, const float* __restrict__ Wt,
       const float* __restrict__ bias, float* __restrict__ Cout, int mode)
{
    __shared__ float As[128][36];   // [m][k], pad 36 -> frag reads conflict-free
    __shared__ float Ws[64][36];    // [n][k]

    const float* __restrict__ Ain = (mode == 1) ? g_attn : A;

    const int tid  = threadIdx.x;
    const int lane = tid & 31, warp = tid >> 5;
    const int g = lane >> 2, tg = lane & 3;
    const int wm = (warp >> 1) * 32;   // 0,32,64,96
    const int wn = (warp & 1) * 32;    // 0,32
    const int rowBase = blockIdx.y * 128;
    const int colBase = blockIdx.x * 64;

    float acc[2][4][4];
#pragma unroll
    for (int mt = 0; mt < 2; mt++)
#pragma unroll
        for (int nt = 0; nt < 4; nt++)
#pragma unroll
            for (int j = 0; j < 4; j++) acc[mt][nt][j] = 0.f;

    for (int kt = 0; kt < Dd; kt += 32) {
        __syncthreads();
#pragma unroll
        for (int t = 0; t < 4; t++) {
            int idx = tid + t * 256;
            int r = idx >> 3, kq = (idx & 7) << 2;
            float4 v = *(const float4*)(Ain + (size_t)(rowBase + r) * Dd + kt + kq);
            As[r][kq] = v.x; As[r][kq + 1] = v.y; As[r][kq + 2] = v.z; As[r][kq + 3] = v.w;
        }
#pragma unroll
        for (int t = 0; t < 2; t++) {
            int idx = tid + t * 256;
            int r = idx >> 3, kq = (idx & 7) << 2;
            float4 v = *(const float4*)(Wt + (size_t)(colBase + r) * Dd + kt + kq);
            Ws[r][kq] = v.x; Ws[r][kq + 1] = v.y; Ws[r][kq + 2] = v.z; Ws[r][kq + 3] = v.w;
        }
        __syncthreads();

#pragma unroll
        for (int ks = 0; ks < 4; ks++) {
            const int k0 = ks * 8;
            HL af[2][4];
#pragma unroll
            for (int mt = 0; mt < 2; mt++) {
                int r0 = wm + mt * 16 + g;
                af[mt][0] = splitf(As[r0][k0 + tg]);
                af[mt][1] = splitf(As[r0 + 8][k0 + tg]);
                af[mt][2] = splitf(As[r0][k0 + tg + 4]);
                af[mt][3] = splitf(As[r0 + 8][k0 + tg + 4]);
            }
#pragma unroll
            for (int nt = 0; nt < 4; nt++) {
                int c0 = wn + nt * 8 + g;
                HL b0 = splitf(Ws[c0][k0 + tg]);
                HL b1 = splitf(Ws[c0][k0 + tg + 4]);
                mma_x3(acc[0][nt], af[0], b0, b1);
                mma_x3(acc[1][nt], af[1], b0, b1);
            }
        }
    }

    // Epilogue: bias + scatter
#pragma unroll
    for (int mt = 0; mt < 2; mt++)
#pragma unroll
    for (int nt = 0; nt < 4; nt++)
#pragma unroll
    for (int hf = 0; hf < 2; hf++) {
        int r = rowBase + wm + mt * 16 + g + hf * 8;
        int c = colBase + wn + nt * 8 + 2 * tg;
        float2 bv = *(const float2*)(bias + c);
        float2 v = make_float2(acc[mt][nt][hf * 2] + bv.x,
                               acc[mt][nt][hf * 2 + 1] + bv.y);
        int bb = r >> 11, s = r & 2047;
        if (mode == 0) {
            if (c < Dd) {
                int h = c >> 6, d0 = c & 63;
                *(float2*)&g_Q[(((size_t)(bb * Hh + h)) * Ss + s) * HDc + d0] = v;
            } else {
                int c2 = c - Dd; int h = c2 >> 6, d0 = c2 & 63;
                *(float2*)&g_K[(((size_t)(bb * Hh + h)) * Ss + s) * HDc + d0] = v;
            }
        } else {
            *(float2*)(Cout + (size_t)r * Dd + c) = v;
        }
    }
}

// ---------------------------------------------------------------------------
// Tensor-core flash attention with multiplicative mask and L1 renorm.
// out[r] = sum_t exp(s-m)*M*V / (sum_t exp(s-m)*M + EPS * sum_t exp(s-m))
// CTA = (b,h, 64-query tile), 128 threads = 4 warps; warp w owns rows
// [16w,16w+16). Both GEMMs 3xTF32. Dynamic smem: Qs/Ks/Ps [64][68], Vs [64][72].
// ---------------------------------------------------------------------------
#define ATTN_SMEM ((3 * 64 * 68 + 64 * 72) * 4)

__global__ void __launch_bounds__(128)
attn_k(const float* __restrict__ Vg, const float* __restrict__ Mg)
{
    extern __shared__ float sm[];
    float* Qs = sm;                          // [64][68]
    float* Ks = sm + 64 * 68;                // [64][68]
    float* Vs = sm + 2 * 64 * 68;            // [64][72] (pad 72 -> B-frag conflict-free)
    float* Ps = sm + 2 * 64 * 68 + 64 * 72;  // [64][68]

    const int tid  = threadIdx.x;
    const int lane = tid & 31, w = tid >> 5;
    const int g = lane >> 2, tg = lane & 3;
    const int bh = blockIdx.y, bb = bh >> 4, h = bh & 15;
    const int q0 = blockIdx.x * 64;
    const int r0 = w * 16 + g;               // this thread's base row (and r0+8)

    // Load Q tile once
    const float* __restrict__ gQ = g_Q + ((size_t)bh * Ss + q0) * HDc;
#pragma unroll
    for (int t = 0; t < 8; t++) {
        int idx = tid + t * 128;
        int r = idx >> 4, d4 = (idx & 15) << 2;
        float4 v = *(const float4*)(gQ + (size_t)r * HDc + d4);
        Qs[r * 68 + d4] = v.x; Qs[r * 68 + d4 + 1] = v.y;
        Qs[r * 68 + d4 + 2] = v.z; Qs[r * 68 + d4 + 3] = v.w;
    }

    float m_cur[2] = {-1e30f, -1e30f}, Zacc[2] = {0.f, 0.f}, Wacc[2] = {0.f, 0.f};
    float oacc[8][4];
#pragma unroll
    for (int nt = 0; nt < 8; nt++)
#pragma unroll
        for (int j = 0; j < 4; j++) oacc[nt][j] = 0.f;

    const float* __restrict__ mrow0 = Mg + ((size_t)(bb * Ss + q0 + r0)) * Ss;
    const float* __restrict__ mrow1 = mrow0 + (size_t)8 * Ss;

    for (int kt = 0; kt < Ss; kt += 64) {
        __syncthreads();   // prev iter's GEMM1/GEMM2 done with Ks/Vs

        // Load K tile [key][d]
        const float* __restrict__ gK = g_K + ((size_t)bh * Ss + kt) * HDc;
#pragma unroll
        for (int t = 0; t < 8; t++) {
            int idx = tid + t * 128;
            int r = idx >> 4, d4 = (idx & 15) << 2;
            float4 v = *(const float4*)(gK + (size_t)r * HDc + d4);
            Ks[r * 68 + d4] = v.x; Ks[r * 68 + d4 + 1] = v.y;
            Ks[r * 68 + d4 + 2] = v.z; Ks[r * 68 + d4 + 3] = v.w;
        }
        // Load V tile [key][d]
        const float* __restrict__ gV = Vg + (((size_t)(bb * Ss + kt)) * Hh + h) * HDc;
#pragma unroll
        for (int t = 0; t < 8; t++) {
            int idx = tid + t * 128;
            int r = idx >> 4, d4 = (idx & 15) << 2;
            float4 v = *(const float4*)(gV + (size_t)r * (Hh * HDc) + d4);
            Vs[r * 72 + d4] = v.x; Vs[r * 72 + d4 + 1] = v.y;
            Vs[r * 72 + d4 + 2] = v.z; Vs[r * 72 + d4 + 3] = v.w;
        }
        // Prefetch mask fragments (hidden under GEMM1)
        float2 mk0[8], mk1[8];
#pragma unroll
        for (int nt = 0; nt < 8; nt++) {
            mk0[nt] = *(const float2*)(mrow0 + kt + nt * 8 + 2 * tg);
            mk1[nt] = *(const float2*)(mrow1 + kt + nt * 8 + 2 * tg);
        }
        __syncthreads();

        // GEMM1: S = Q K^T  (A=Q row-major, B=K^T col-major -> read K[key][d])
        float sfr[8][4];
#pragma unroll
        for (int nt = 0; nt < 8; nt++)
#pragma unroll
            for (int j = 0; j < 4; j++) sfr[nt][j] = 0.f;
#pragma unroll
        for (int ks = 0; ks < 8; ks++) {
            const int k0 = ks * 8;
            HL qf[4];
            qf[0] = splitf(Qs[r0 * 68 + k0 + tg]);
            qf[1] = splitf(Qs[(r0 + 8) * 68 + k0 + tg]);
            qf[2] = splitf(Qs[r0 * 68 + k0 + tg + 4]);
            qf[3] = splitf(Qs[(r0 + 8) * 68 + k0 + tg + 4]);
#pragma unroll
            for (int nt = 0; nt < 8; nt++) {
                int c = nt * 8 + g;
                HL b0 = splitf(Ks[c * 68 + k0 + tg]);
                HL b1 = splitf(Ks[c * 68 + k0 + tg + 4]);
                mma_x3(sfr[nt], qf, b0, b1);
            }
        }

        // Softmax stats (rows r0 and r0+8; reduce over 4-thread group)
        float rmax0 = -1e30f, rmax1 = -1e30f;
#pragma unroll
        for (int nt = 0; nt < 8; nt++) {
            sfr[nt][0] *= SCALE; sfr[nt][1] *= SCALE;
            sfr[nt][2] *= SCALE; sfr[nt][3] *= SCALE;
            rmax0 = fmaxf(rmax0, fmaxf(sfr[nt][0], sfr[nt][1]));
            rmax1 = fmaxf(rmax1, fmaxf(sfr[nt][2], sfr[nt][3]));
        }
        rmax0 = fmaxf(rmax0, __shfl_xor_sync(0xffffffffu, rmax0, 1));
        rmax0 = fmaxf(rmax0, __shfl_xor_sync(0xffffffffu, rmax0, 2));
        rmax1 = fmaxf(rmax1, __shfl_xor_sync(0xffffffffu, rmax1, 1));
        rmax1 = fmaxf(rmax1, __shfl_xor_sync(0xffffffffu, rmax1, 2));
        float mn0 = fmaxf(m_cur[0], rmax0), mn1 = fmaxf(m_cur[1], rmax1);
        float al0 = __expf(m_cur[0] - mn0), al1 = __expf(m_cur[1] - mn1);

        float zp0 = 0.f, zp1 = 0.f, wp0 = 0.f, wp1 = 0.f;
#pragma unroll
        for (int nt = 0; nt < 8; nt++) {
            float p00 = __expf(sfr[nt][0] - mn0), p01 = __expf(sfr[nt][1] - mn0);
            float p10 = __expf(sfr[nt][2] - mn1), p11 = __expf(sfr[nt][3] - mn1);
            zp0 += p00 + p01; zp1 += p10 + p11;
            float w00 = p00 * mk0[nt].x, w01 = p01 * mk0[nt].y;
            float w10 = p10 * mk1[nt].x, w11 = p11 * mk1[nt].y;
            wp0 += w00 + w01; wp1 += w10 + w11;
            int c = nt * 8 + 2 * tg;
            *(float2*)&Ps[r0 * 68 + c]       = make_float2(w00, w01);
            *(float2*)&Ps[(r0 + 8) * 68 + c] = make_float2(w10, w11);
        }
        zp0 += __shfl_xor_sync(0xffffffffu, zp0, 1); zp0 += __shfl_xor_sync(0xffffffffu, zp0, 2);
        zp1 += __shfl_xor_sync(0xffffffffu, zp1, 1); zp1 += __shfl_xor_sync(0xffffffffu, zp1, 2);
        wp0 += __shfl_xor_sync(0xffffffffu, wp0, 1); wp0 += __shfl_xor_sync(0xffffffffu, wp0, 2);
        wp1 += __shfl_xor_sync(0xffffffffu, wp1, 1); wp1 += __shfl_xor_sync(0xffffffffu, wp1, 2);
        Zacc[0] = Zacc[0] * al0 + zp0; Zacc[1] = Zacc[1] * al1 + zp1;
        Wacc[0] = Wacc[0] * al0 + wp0; Wacc[1] = Wacc[1] * al1 + wp1;
        m_cur[0] = mn0; m_cur[1] = mn1;
        __syncwarp();   // Ps rows are warp-private; make stores visible in-warp

        // GEMM2: O = O*alpha + P V  (A=P row-major, B=V col-major -> V[key][d])
#pragma unroll
        for (int nt = 0; nt < 8; nt++) {
            oacc[nt][0] *= al0; oacc[nt][1] *= al0;
            oacc[nt][2] *= al1; oacc[nt][3] *= al1;
        }
#pragma unroll
        for (int ks = 0; ks < 8; ks++) {
            const int k0 = ks * 8;
            HL pf[4];
            pf[0] = splitf(Ps[r0 * 68 + k0 + tg]);
            pf[1] = splitf(Ps[(r0 + 8) * 68 + k0 + tg]);
            pf[2] = splitf(Ps[r0 * 68 + k0 + tg + 4]);
            pf[3] = splitf(Ps[(r0 + 8) * 68 + k0 + tg + 4]);
#pragma unroll
            for (int nt = 0; nt < 8; nt++) {
                HL b0 = splitf(Vs[(k0 + tg) * 72 + nt * 8 + g]);
                HL b1 = splitf(Vs[(k0 + tg + 4) * 72 + nt * 8 + g]);
                mma_x3(oacc[nt], pf, b0, b1);
            }
        }
    }

    // Epilogue: divide and write [B,S,D]
    float inv0 = 1.f / (Wacc[0] + 1e-8f * Zacc[0]);
    float inv1 = 1.f / (Wacc[1] + 1e-8f * Zacc[1]);
    int s0 = q0 + r0;
#pragma unroll
    for (int nt = 0; nt < 8; nt++) {
        int c = h * HDc + nt * 8 + 2 * tg;
        *(float2*)&g_attn[((size_t)(bb * Ss + s0)) * Dd + c] =
            make_float2(oacc[nt][0] * inv0, oacc[nt][1] * inv0);
        *(float2*)&g_attn[((size_t)(bb * Ss + s0 + 8)) * Dd + c] =
            make_float2(oacc[nt][2] * inv1, oacc[nt][3] * inv1);
    }
}

// ---------------------------------------------------------------------------
extern "C" void kernel_launch(void* const* d_in, const int* in_sizes, int n_in,
                              void* d_out, int out_size)
{
    const float* x     = (const float*)d_in[0];
    const float* V     = (const float*)d_in[1];
    const float* M     = (const float*)d_in[2];
    const float* in_w  = (const float*)d_in[3];
    const float* in_b  = (const float*)d_in[4];
    const float* out_w = (const float*)d_in[5];
    const float* out_b = (const float*)d_in[6];
    float* out = (float*)d_out;

    // Opt-in to 69KB dynamic smem for the attention kernel (deterministic,
    // executes immediately; not a stream op, so graph capture is unaffected).
    cudaFuncSetAttribute((const void*)attn_k,
                         cudaFuncAttributeMaxDynamicSharedMemorySize, ATTN_SMEM);

    // 1) QK projection: [4096,1024] x [2048,1024]^T -> scatter to g_Q/g_K
    proj_k<<<dim3(32, 32), 256>>>(x, in_w, in_b, nullptr, 0);
    // 2) masked-renorm flash attention (3xTF32 tensor cores) -> g_attn
    attn_k<<<dim3(32, 32), 128, ATTN_SMEM>>>(V, M);
    // 3) out projection: g_attn x out_w^T + out_b -> d_out
    proj_k<<<dim3(16, 32), 256>>>(nullptr, out_w, out_b, out, 1);
}